// round 1
// baseline (speedup 1.0000x reference)
#include <cuda_runtime.h>
#include <math.h>
#include <limits.h>
#include <stdint.h>

#define BB 8
#define KK 512
#define DD 16
#define MAX_CPN 512
#define CPBUF 1024
#define ATTR_W 1.0f
#define REPL_W 1.0f
#define BG_W 2.0f

#define PPB 4096   // points per block in main pass
#define TPB 256
#define RTJ 16     // repulsion j-tile

// ---------------- device scratch (no allocation allowed) ----------------
__device__ int   g_cnt[BB*KK];
__device__ int   g_cpcnt[BB*KK];
__device__ int   g_fi[BB*KK];
__device__ float g_cpbeta[BB*KK];
__device__ float g_sumexp[BB*KK];
__device__ float g_sumsq[BB*KK];
__device__ float g_sume[BB*KK*DD];
__device__ int   g_ncp[BB];
__device__ int   g_nbg[BB];
__device__ float g_bgsig[BB];
__device__ int   g_cpidx[BB*CPBUF];
__device__ float g_rep[BB];
__device__ float g_batch[BB*5];

// ---------------- zero pass (graph replays reuse scratch) ----------------
__global__ void zero_kernel() {
    int idx = blockIdx.x * blockDim.x + threadIdx.x;
    int stride = gridDim.x * blockDim.x;
    for (int i = idx; i < BB*KK; i += stride) {
        g_cnt[i] = 0; g_cpcnt[i] = 0; g_fi[i] = INT_MAX;
        g_cpbeta[i] = 0.f; g_sumexp[i] = 0.f; g_sumsq[i] = 0.f;
    }
    for (int i = idx; i < BB*KK*DD; i += stride) g_sume[i] = 0.f;
    if (idx < BB) { g_ncp[idx] = 0; g_nbg[idx] = 0; g_bgsig[idx] = 0.f; g_rep[idx] = 0.f; }
}

// ---------------- single big pass over all inputs ----------------
__global__ void __launch_bounds__(TPB)
main_pass(const float* __restrict__ beta, const float* __restrict__ embed,
          const int* __restrict__ sid, const int* __restrict__ iscp, int N) {
    __shared__ int   s_cnt[KK];
    __shared__ int   s_cpcnt[KK];
    __shared__ int   s_fi[KK];
    __shared__ float s_cpbeta[KK];
    __shared__ float s_sumexp[KK];
    __shared__ float s_sumsq[KK];
    __shared__ float s_sume[KK*DD];       // 32 KB
    __shared__ float s_bgs;
    __shared__ int   s_bgc;

    int b = blockIdx.y;
    int t = threadIdx.x;
    for (int k = t; k < KK; k += TPB) {
        s_cnt[k] = 0; s_cpcnt[k] = 0; s_fi[k] = INT_MAX;
        s_cpbeta[k] = 0.f; s_sumexp[k] = 0.f; s_sumsq[k] = 0.f;
    }
    for (int k = t; k < KK*DD; k += TPB) s_sume[k] = 0.f;
    if (t == 0) { s_bgs = 0.f; s_bgc = 0; }
    __syncthreads();

    const float* betB = beta  + (size_t)b * N;
    const float* embB = embed + (size_t)b * N * DD;
    const int*   sidB = sid   + (size_t)b * N;
    const int*   cpB  = iscp  + (size_t)b * N;

    int base = blockIdx.x * PPB;
    int end  = min(base + PPB, N);
    float bgs = 0.f; int bgc = 0;

    for (int i = base + t; i < end; i += TPB) {
        int   s  = sidB[i];
        float bt = betB[i];
        int   cp = cpB[i];
        if ((unsigned)s < (unsigned)KK) {   // foreground
            const float4* ep = (const float4*)(embB + (size_t)i * DD);
            float4 e0 = ep[0], e1 = ep[1], e2 = ep[2], e3 = ep[3];
            float sq = e0.x*e0.x + e0.y*e0.y + e0.z*e0.z + e0.w*e0.w
                     + e1.x*e1.x + e1.y*e1.y + e1.z*e1.z + e1.w*e1.w
                     + e2.x*e2.x + e2.y*e2.y + e2.z*e2.z + e2.w*e2.w
                     + e3.x*e3.x + e3.y*e3.y + e3.z*e3.z + e3.w*e3.w;
            atomicAdd(&s_cnt[s], 1);
            atomicAdd(&s_sumexp[s], __expf(bt));
            atomicAdd(&s_sumsq[s], sq);
            float* su = &s_sume[s * DD];
            atomicAdd(su+0,  e0.x); atomicAdd(su+1,  e0.y); atomicAdd(su+2,  e0.z); atomicAdd(su+3,  e0.w);
            atomicAdd(su+4,  e1.x); atomicAdd(su+5,  e1.y); atomicAdd(su+6,  e1.z); atomicAdd(su+7,  e1.w);
            atomicAdd(su+8,  e2.x); atomicAdd(su+9,  e2.y); atomicAdd(su+10, e2.z); atomicAdd(su+11, e2.w);
            atomicAdd(su+12, e3.x); atomicAdd(su+13, e3.y); atomicAdd(su+14, e3.z); atomicAdd(su+15, e3.w);
            if (cp == 1) {
                atomicAdd(&s_cpcnt[s], 1);
                atomicAdd(&s_cpbeta[s], bt);
                atomicMin(&s_fi[s], i);
            }
        } else {                              // background
            bgc++; bgs += 1.f / (1.f + __expf(-bt));
        }
        if (cp == 1) {                        // cp_all (independent of fg)
            int pos = atomicAdd(&g_ncp[b], 1);
            if (pos < CPBUF) g_cpidx[b*CPBUF + pos] = i;
        }
    }
    atomicAdd(&s_bgs, bgs);
    atomicAdd(&s_bgc, bgc);
    __syncthreads();

    // flush block-local segment stats
    for (int k = t; k < KK; k += TPB) {
        int c = s_cnt[k];
        int gi = b*KK + k;
        if (c > 0) {
            atomicAdd(&g_cnt[gi], c);
            atomicAdd(&g_sumexp[gi], s_sumexp[k]);
            atomicAdd(&g_sumsq[gi], s_sumsq[k]);
            #pragma unroll
            for (int d = 0; d < DD; d++) atomicAdd(&g_sume[gi*DD + d], s_sume[k*DD + d]);
        }
        if (s_cpcnt[k] > 0) {
            atomicAdd(&g_cpcnt[gi], s_cpcnt[k]);
            atomicAdd(&g_cpbeta[gi], s_cpbeta[k]);
            atomicMin(&g_fi[gi], s_fi[k]);
        }
    }
    if (t == 0 && s_bgc > 0) {
        atomicAdd(&g_nbg[b], s_bgc);
        atomicAdd(&g_bgsig[b], s_bgs);
    }
}

// ---------------- sort cp indices ascending (set-determinism + ncp>MAX_CP truncation) ----------------
__global__ void __launch_bounds__(512) sort_cp() {
    int b = blockIdx.x;
    __shared__ int arr[CPBUF];
    int cnt = g_ncp[b]; if (cnt > CPBUF) cnt = CPBUF;
    int t = threadIdx.x;
    for (int i = t; i < CPBUF; i += 512) arr[i] = (i < cnt) ? g_cpidx[b*CPBUF + i] : INT_MAX;
    __syncthreads();
    for (int k = 2; k <= CPBUF; k <<= 1) {
        for (int j = k >> 1; j > 0; j >>= 1) {
            for (int i = t; i < CPBUF; i += 512) {
                int ixj = i ^ j;
                if (ixj > i) {
                    int a = arr[i], c = arr[ixj];
                    bool up = ((i & k) == 0);
                    if ((a > c) == up) { arr[i] = c; arr[ixj] = a; }
                }
            }
            __syncthreads();
        }
    }
    for (int i = t; i < cnt; i += 512) g_cpidx[b*CPBUF + i] = arr[i];
}

// ---------------- repulsion: tiled P x P pairwise exp(-dist2) ----------------
__global__ void __launch_bounds__(256)
rep_kernel(const float* __restrict__ embed, int N) {
    int b = blockIdx.x;
    int P = g_ncp[b]; if (P > MAX_CPN) P = MAX_CPN;
    int j0 = blockIdx.y * RTJ;
    if (j0 >= P) return;

    __shared__ float ej[RTJ*DD];
    int t = threadIdx.x;
    if (t < RTJ*DD) {
        int jj = j0 + t / DD;
        float v = 0.f;
        if (jj < P) {
            int idx = g_cpidx[b*CPBUF + jj];
            v = embed[(size_t)b*N*DD + (size_t)idx*DD + (t % DD)];
        }
        ej[t] = v;
    }
    __syncthreads();

    int jend = min(RTJ, P - j0);
    float acc = 0.f;
    #pragma unroll
    for (int r = 0; r < 2; r++) {
        int i = t + r * 256;
        if (i < P) {
            int idx = g_cpidx[b*CPBUF + i];
            const float4* ep = (const float4*)(embed + (size_t)b*N*DD + (size_t)idx*DD);
            float4 a0 = ep[0], a1 = ep[1], a2 = ep[2], a3 = ep[3];
            float ei[DD] = { a0.x,a0.y,a0.z,a0.w, a1.x,a1.y,a1.z,a1.w,
                             a2.x,a2.y,a2.z,a2.w, a3.x,a3.y,a3.z,a3.w };
            for (int j = 0; j < jend; j++) {
                float ds = 0.f;
                #pragma unroll
                for (int d = 0; d < DD; d++) { float df = ei[d] - ej[j*DD + d]; ds += df*df; }
                acc += __expf(-ds);
            }
        }
    }
    // block reduce
    for (int o = 16; o > 0; o >>= 1) acc += __shfl_down_sync(0xffffffffu, acc, o);
    __shared__ float wsum[8];
    if ((t & 31) == 0) wsum[t >> 5] = acc;
    __syncthreads();
    if (t < 8) {
        float v = wsum[t];
        for (int o = 4; o > 0; o >>= 1) v += __shfl_down_sync(0xffu, v, o);
        if (t == 0) atomicAdd(&g_rep[b], v);
    }
}

// ---------------- per-batch finalize ----------------
__global__ void __launch_bounds__(512)
finalize_kernel(const float* __restrict__ embed, int N) {
    int b = blockIdx.x, k = threadIdx.x;
    int gi = b*KK + k;
    int cnt = g_cnt[gi], cpc = g_cpcnt[gi];
    float ce = 0.f, attr_k = 0.f; int vld = 0;
    if (cnt > 0 && cpc == 1) {
        vld = 1;
        ce = __logf(fmaxf(g_sumexp[gi], 1e-30f)) - g_cpbeta[gi];
    }
    if (cnt > 0 && cpc >= 1) {
        int fi = g_fi[gi];
        const float* r = embed + (size_t)b*N*DD + (size_t)fi*DD;
        float rr = 0.f, rd = 0.f;
        #pragma unroll
        for (int d = 0; d < DD; d++) { float rv = r[d]; rr += rv*rv; rd += rv * g_sume[gi*DD + d]; }
        float ds = g_sumsq[gi] - 2.f*rd + (float)cnt * rr;
        attr_k = ds / fmaxf((float)cnt, 1.f);
    }
    __shared__ float s1[512], s2[512];
    __shared__ int   s3[512];
    s1[k] = ce; s2[k] = attr_k; s3[k] = vld;
    __syncthreads();
    for (int o = 256; o > 0; o >>= 1) {
        if (k < o) { s1[k] += s1[k+o]; s2[k] += s2[k+o]; s3[k] += s3[k+o]; }
        __syncthreads();
    }
    if (k == 0) {
        int sc = s3[0];
        float bl = s1[0] / fmaxf((float)sc, 1.f);
        int nbg = g_nbg[b];
        if (nbg > 0) bl += BG_W * (g_bgsig[b] / (float)nbg);
        float attr = ATTR_W * s2[0];
        int ncp = g_ncp[b];
        float rep = (ncp > 1) ? REPL_W * g_rep[b] / fmaxf((float)ncp * (float)ncp, 1.f) : 0.f;
        g_batch[b*5 + 0] = bl + attr + rep;
        g_batch[b*5 + 1] = bl;
        g_batch[b*5 + 2] = attr;
        g_batch[b*5 + 3] = rep;
        g_batch[b*5 + 4] = (sc > 0) ? 1.f : 0.f;
    }
}

// ---------------- cross-batch reduce ----------------
__global__ void final_kernel(float* out, int out_size) {
    if (threadIdx.x == 0 && blockIdx.x == 0) {
        float cnt = 0.f, t0 = 0.f, t1 = 0.f, t2 = 0.f, t3 = 0.f;
        for (int b = 0; b < BB; b++) {
            float inc = g_batch[b*5 + 4];
            cnt += inc;
            t0 += g_batch[b*5 + 0] * inc;
            t1 += g_batch[b*5 + 1] * inc;
            t2 += g_batch[b*5 + 2] * inc;
            t3 += g_batch[b*5 + 3] * inc;
        }
        float den = fmaxf(cnt, 1.f);
        if (out_size > 0) out[0] = (cnt > 0.f) ? t0 / den : 0.f;
        if (out_size > 1) out[1] = t1 / den;
        if (out_size > 2) out[2] = t2 / den;
        if (out_size > 3) out[3] = t3 / den;
    }
}

extern "C" void kernel_launch(void* const* d_in, const int* in_sizes, int n_in,
                              void* d_out, int out_size) {
    const float* beta  = (const float*)d_in[0];
    const float* embed = (const float*)d_in[1];
    const int*   sid   = (const int*)d_in[2];
    const int*   iscp  = (const int*)d_in[3];
    int N = in_sizes[0] / BB;

    zero_kernel<<<64, 256>>>();
    dim3 g1((N + PPB - 1) / PPB, BB);
    main_pass<<<g1, TPB>>>(beta, embed, sid, iscp, N);
    sort_cp<<<BB, 512>>>();
    dim3 g2(BB, MAX_CPN / RTJ);
    rep_kernel<<<g2, 256>>>(embed, N);
    finalize_kernel<<<BB, 512>>>(embed, N);
    final_kernel<<<1, 32>>>((float*)d_out, out_size);
}

// round 2
// speedup vs baseline: 1.8893x; 1.8893x over previous
#include <cuda_runtime.h>
#include <math.h>
#include <limits.h>
#include <stdint.h>

#define BB 8
#define KK 512
#define DD 16
#define MAX_CPN 512
#define CPBUF 1024
#define ATTR_W 1.0f
#define REPL_W 1.0f
#define BG_W 2.0f

#define PPA 8192
#define PPC 2048
#define TPB 256

// ---------------- device scratch (no allocation allowed) ----------------
__device__ float4 g_acc[BB*KK];        // {cnt, sumexp, dsum, pad}
__device__ int    g_cpcnt[BB*KK];
__device__ int    g_fi[BB*KK];
__device__ float  g_cpbeta[BB*KK];
__device__ float  g_ref[BB*KK*DD];     // gathered reference embeddings
__device__ int    g_ncp[BB];
__device__ int    g_nbg[BB];
__device__ float  g_bgsig[BB];
__device__ int    g_cpidx[BB*CPBUF];
__device__ float  g_rep[BB];
__device__ float  g_batch[BB*5];

// ---------------- zero pass ----------------
__global__ void zero_kernel() {
    int idx = blockIdx.x * blockDim.x + threadIdx.x;
    int stride = gridDim.x * blockDim.x;
    for (int i = idx; i < BB*KK; i += stride) {
        g_acc[i] = make_float4(0.f, 0.f, 0.f, 0.f);
        g_cpcnt[i] = 0; g_fi[i] = INT_MAX; g_cpbeta[i] = 0.f;
    }
    if (idx < BB) { g_ncp[idx] = 0; g_nbg[idx] = 0; g_bgsig[idx] = 0.f; g_rep[idx] = 0.f; }
}

// ---------------- pass A: cp-segment stats + bg stats (light arrays only) ----------------
__global__ void __launch_bounds__(TPB)
pass_a(const float* __restrict__ beta, const int* __restrict__ sid,
       const int* __restrict__ iscp, int N) {
    int b = blockIdx.y;
    int t = threadIdx.x;
    const float* betB = beta + (size_t)b * N;
    const int*   sidB = sid  + (size_t)b * N;
    const int*   cpB  = iscp + (size_t)b * N;

    int base = blockIdx.x * PPA;
    int end  = min(base + PPA, N);
    float bgs = 0.f; int bgc = 0;

    for (int i = base + t; i < end; i += TPB) {
        int s  = sidB[i];
        int cp = cpB[i];
        bool fg = (unsigned)s < (unsigned)KK;
        if (!fg) {
            float bt = betB[i];
            bgc++; bgs += 1.f / (1.f + __expf(-bt));
        }
        if (cp == 1) {
            if (fg) {
                float bt = betB[i];
                int gi = b*KK + s;
                atomicAdd(&g_cpcnt[gi], 1);
                atomicAdd(&g_cpbeta[gi], bt);
                atomicMin(&g_fi[gi], i);
            }
            int pos = atomicAdd(&g_ncp[b], 1);
            if (pos < CPBUF) g_cpidx[b*CPBUF + pos] = i;
        }
    }
    // block-reduce bg stats
    for (int o = 16; o > 0; o >>= 1) {
        bgs += __shfl_down_sync(0xffffffffu, bgs, o);
        bgc += __shfl_down_sync(0xffffffffu, bgc, o);
    }
    __shared__ float sw[8]; __shared__ int swc[8];
    if ((t & 31) == 0) { sw[t >> 5] = bgs; swc[t >> 5] = bgc; }
    __syncthreads();
    if (t < 8) {
        float v = sw[t]; int c = swc[t];
        for (int o = 4; o > 0; o >>= 1) {
            v += __shfl_down_sync(0xffu, v, o);
            c += __shfl_down_sync(0xffu, c, o);
        }
        if (t == 0 && c > 0) { atomicAdd(&g_bgsig[b], v); atomicAdd(&g_nbg[b], c); }
    }
}

// ---------------- pass B: gather reference embeddings ----------------
__global__ void __launch_bounds__(512)
gather_ref(const float* __restrict__ embed, int N) {
    int b = blockIdx.x, k = threadIdx.x;
    int gi = b*KK + k;
    int fi = g_fi[gi];
    float4* dst = (float4*)&g_ref[gi*DD];
    if (g_cpcnt[gi] >= 1 && fi != INT_MAX) {
        const float4* src = (const float4*)(embed + (size_t)b*N*DD + (size_t)fi*DD);
        dst[0] = src[0]; dst[1] = src[1]; dst[2] = src[2]; dst[3] = src[3];
    } else {
        float4 z = make_float4(0.f,0.f,0.f,0.f);
        dst[0] = z; dst[1] = z; dst[2] = z; dst[3] = z;
    }
}

// ---------------- pass C: big stream over embed, single vector-RED per point ----------------
__global__ void __launch_bounds__(TPB)
pass_c(const float* __restrict__ beta, const float* __restrict__ embed,
       const int* __restrict__ sid, int N) {
    __shared__ float4 s_ref[KK*4];   // 32 KB: all 512 ref vectors for this batch
    int b = blockIdx.y;
    int t = threadIdx.x;
    const float4* gr = (const float4*)&g_ref[(size_t)b*KK*DD];
    for (int k = t; k < KK*4; k += TPB) s_ref[k] = gr[k];
    __syncthreads();

    const float* betB = beta  + (size_t)b * N;
    const float* embB = embed + (size_t)b * N * DD;
    const int*   sidB = sid   + (size_t)b * N;

    int base = blockIdx.x * PPC;
    int end  = min(base + PPC, N);

    for (int i = base + t; i < end; i += TPB) {
        int s = sidB[i];
        if ((unsigned)s < (unsigned)KK) {
            float bt = betB[i];
            const float4* ep = (const float4*)(embB + (size_t)i * DD);
            float4 e0 = ep[0], e1 = ep[1], e2 = ep[2], e3 = ep[3];
            float4 r0 = s_ref[s*4+0], r1 = s_ref[s*4+1], r2 = s_ref[s*4+2], r3 = s_ref[s*4+3];
            float d = 0.f, df;
            df = e0.x-r0.x; d += df*df; df = e0.y-r0.y; d += df*df;
            df = e0.z-r0.z; d += df*df; df = e0.w-r0.w; d += df*df;
            df = e1.x-r1.x; d += df*df; df = e1.y-r1.y; d += df*df;
            df = e1.z-r1.z; d += df*df; df = e1.w-r1.w; d += df*df;
            df = e2.x-r2.x; d += df*df; df = e2.y-r2.y; d += df*df;
            df = e2.z-r2.z; d += df*df; df = e2.w-r2.w; d += df*df;
            df = e3.x-r3.x; d += df*df; df = e3.y-r3.y; d += df*df;
            df = e3.z-r3.z; d += df*df; df = e3.w-r3.w; d += df*df;
            atomicAdd(&g_acc[b*KK + s], make_float4(1.f, __expf(bt), d, 0.f));
        }
    }
}

// ---------------- sort cp indices (only needed if ncp > MAX_CP; guarded no-op here) ----------------
__global__ void __launch_bounds__(512) sort_cp() {
    int b = blockIdx.x;
    int cnt = g_ncp[b]; if (cnt > CPBUF) cnt = CPBUF;
    if (cnt <= MAX_CPN) return;   // pairwise sum is set-invariant; sort only matters for truncation
    __shared__ int arr[CPBUF];
    int t = threadIdx.x;
    for (int i = t; i < CPBUF; i += 512) arr[i] = (i < cnt) ? g_cpidx[b*CPBUF + i] : INT_MAX;
    __syncthreads();
    for (int k = 2; k <= CPBUF; k <<= 1) {
        for (int j = k >> 1; j > 0; j >>= 1) {
            for (int i = t; i < CPBUF; i += 512) {
                int ixj = i ^ j;
                if (ixj > i) {
                    int a = arr[i], c = arr[ixj];
                    bool up = ((i & k) == 0);
                    if ((a > c) == up) { arr[i] = c; arr[ixj] = a; }
                }
            }
            __syncthreads();
        }
    }
    for (int i = t; i < cnt; i += 512) g_cpidx[b*CPBUF + i] = arr[i];
}

// ---------------- repulsion: all cp embeddings in shared, register i-rows ----------------
#define RI 32
__global__ void __launch_bounds__(256)
rep_kernel(const float* __restrict__ embed, int N) {
    int b = blockIdx.x;
    int P = g_ncp[b]; if (P > MAX_CPN) P = MAX_CPN;
    int t = threadIdx.x;

    __shared__ float4 s_e[KK*4];   // 32 KB: all cp embeddings
    const float4* embB = (const float4*)(embed + (size_t)b*N*DD);
    for (int k = t; k < KK*4; k += 256) {
        int jj = k >> 2;
        float4 v = make_float4(0.f,0.f,0.f,0.f);
        if (jj < P) {
            int idx = g_cpidx[b*CPBUF + jj];
            v = embB[(size_t)idx*4 + (k & 3)];
        }
        s_e[k] = v;
    }
    __syncthreads();

    // thread (i_local, strip): i = by*32 + t/8 ; j = (t%8)*64 + jj
    int i = blockIdx.y * RI + (t >> 3);
    int strip = t & 7;
    float acc = 0.f;
    if (i < P) {
        float4 a0 = s_e[i*4+0], a1 = s_e[i*4+1], a2 = s_e[i*4+2], a3 = s_e[i*4+3];
        int j0 = strip * 64;
        #pragma unroll 4
        for (int jj = 0; jj < 64; jj++) {
            int j = j0 + jj;
            if (j < P) {
                float4 b0 = s_e[j*4+0], b1 = s_e[j*4+1], b2 = s_e[j*4+2], b3 = s_e[j*4+3];
                float ds = 0.f, df;
                df = a0.x-b0.x; ds += df*df; df = a0.y-b0.y; ds += df*df;
                df = a0.z-b0.z; ds += df*df; df = a0.w-b0.w; ds += df*df;
                df = a1.x-b1.x; ds += df*df; df = a1.y-b1.y; ds += df*df;
                df = a1.z-b1.z; ds += df*df; df = a1.w-b1.w; ds += df*df;
                df = a2.x-b2.x; ds += df*df; df = a2.y-b2.y; ds += df*df;
                df = a2.z-b2.z; ds += df*df; df = a2.w-b2.w; ds += df*df;
                df = a3.x-b3.x; ds += df*df; df = a3.y-b3.y; ds += df*df;
                df = a3.z-b3.z; ds += df*df; df = a3.w-b3.w; ds += df*df;
                if (ds < 30.f) acc += __expf(-ds);   // exp(-30)=9e-14: negligible vs sum
            }
        }
    }
    // block reduce
    for (int o = 16; o > 0; o >>= 1) acc += __shfl_down_sync(0xffffffffu, acc, o);
    __shared__ float wsum[8];
    if ((t & 31) == 0) wsum[t >> 5] = acc;
    __syncthreads();
    if (t < 8) {
        float v = wsum[t];
        for (int o = 4; o > 0; o >>= 1) v += __shfl_down_sync(0xffu, v, o);
        if (t == 0) atomicAdd(&g_rep[b], v);
    }
}

// ---------------- per-batch finalize ----------------
__global__ void __launch_bounds__(512)
finalize_kernel() {
    int b = blockIdx.x, k = threadIdx.x;
    int gi = b*KK + k;
    float4 a = g_acc[gi];
    float cnt = a.x, sumexp = a.y, dsum = a.z;
    int cpc = g_cpcnt[gi];
    float ce = 0.f, attr_k = 0.f; int vld = 0;
    if (cnt > 0.f && cpc == 1) {
        vld = 1;
        ce = __logf(fmaxf(sumexp, 1e-30f)) - g_cpbeta[gi];
    }
    if (cnt > 0.f && cpc >= 1) {
        attr_k = dsum / fmaxf(cnt, 1.f);
    }
    __shared__ float s1[512], s2[512];
    __shared__ int   s3[512];
    s1[k] = ce; s2[k] = attr_k; s3[k] = vld;
    __syncthreads();
    for (int o = 256; o > 0; o >>= 1) {
        if (k < o) { s1[k] += s1[k+o]; s2[k] += s2[k+o]; s3[k] += s3[k+o]; }
        __syncthreads();
    }
    if (k == 0) {
        int sc = s3[0];
        float bl = s1[0] / fmaxf((float)sc, 1.f);
        int nbg = g_nbg[b];
        if (nbg > 0) bl += BG_W * (g_bgsig[b] / (float)nbg);
        float attr = ATTR_W * s2[0];
        int ncp = g_ncp[b];
        float rep = (ncp > 1) ? REPL_W * g_rep[b] / fmaxf((float)ncp * (float)ncp, 1.f) : 0.f;
        g_batch[b*5 + 0] = bl + attr + rep;
        g_batch[b*5 + 1] = bl;
        g_batch[b*5 + 2] = attr;
        g_batch[b*5 + 3] = rep;
        g_batch[b*5 + 4] = (sc > 0) ? 1.f : 0.f;
    }
}

// ---------------- cross-batch reduce ----------------
__global__ void final_kernel(float* out, int out_size) {
    if (threadIdx.x == 0 && blockIdx.x == 0) {
        float cnt = 0.f, t0 = 0.f, t1 = 0.f, t2 = 0.f, t3 = 0.f;
        for (int b = 0; b < BB; b++) {
            float inc = g_batch[b*5 + 4];
            cnt += inc;
            t0 += g_batch[b*5 + 0] * inc;
            t1 += g_batch[b*5 + 1] * inc;
            t2 += g_batch[b*5 + 2] * inc;
            t3 += g_batch[b*5 + 3] * inc;
        }
        float den = fmaxf(cnt, 1.f);
        if (out_size > 0) out[0] = (cnt > 0.f) ? t0 / den : 0.f;
        if (out_size > 1) out[1] = t1 / den;
        if (out_size > 2) out[2] = t2 / den;
        if (out_size > 3) out[3] = t3 / den;
    }
}

extern "C" void kernel_launch(void* const* d_in, const int* in_sizes, int n_in,
                              void* d_out, int out_size) {
    const float* beta  = (const float*)d_in[0];
    const float* embed = (const float*)d_in[1];
    const int*   sid   = (const int*)d_in[2];
    const int*   iscp  = (const int*)d_in[3];
    int N = in_sizes[0] / BB;

    zero_kernel<<<64, 256>>>();
    dim3 ga((N + PPA - 1) / PPA, BB);
    pass_a<<<ga, TPB>>>(beta, sid, iscp, N);
    gather_ref<<<BB, 512>>>(embed, N);
    dim3 gc((N + PPC - 1) / PPC, BB);
    pass_c<<<gc, TPB>>>(beta, embed, sid, N);
    sort_cp<<<BB, 512>>>();
    dim3 gr(BB, MAX_CPN / RI);
    rep_kernel<<<gr, 256>>>(embed, N);
    finalize_kernel<<<BB, 512>>>();
    final_kernel<<<1, 32>>>((float*)d_out, out_size);
}